// round 1
// baseline (speedup 1.0000x reference)
#include <cuda_runtime.h>
#include <math.h>

#define NN 65536
#define EE 524288
#define NBLK 2
#define NHD 4
#define NCL 4
#define FEAT 64
#define EMB 128
#define OUTD 32
#define GB 256
#define GSZ 256

// ---------------- scratch (static device globals; no allocation) ----------------
__device__ int g_deg[NN];
__device__ int g_off[NN + 1];
__device__ int g_pos[NN];
__device__ int g_csr[EE];
__device__ int g_part[64];
__device__ int g_partoff[64];
__device__ float g_agg[NN * FEAT];
__device__ float g_cur[(size_t)NN * EMB];
__device__ float g_new[(size_t)NN * EMB];
__device__ unsigned g_aggkey[(size_t)NHD * NN * EMB];
__device__ float g_scores[NHD * NN];
__device__ float g_smv[NHD * NN];
__device__ unsigned char g_keep[NHD * NN];
__device__ int g_klist[NHD * NN];
__device__ int g_kcnt[NHD];
__device__ float g_p1[128 * 128];
__device__ float g_p2[128 * 128];
__device__ float g_mu[EMB];
__device__ float g_rinv[EMB];
__device__ float g_bsum[EMB];
__device__ float g_bsumsq[EMB];
__device__ float g_logits[GB * NCL];

__device__ __forceinline__ float lrelu(float v) { return v > 0.f ? v : 0.01f * v; }
// order-preserving float->uint encoding for atomic max; 0 is reserved as "empty"
__device__ __forceinline__ unsigned fenc(float f) {
    unsigned u = __float_as_uint(f);
    return (u & 0x80000000u) ? ~u : (u | 0x80000000u);
}
__device__ __forceinline__ float fdec(unsigned k) {
    return (k & 0x80000000u) ? __uint_as_float(k ^ 0x80000000u) : __uint_as_float(~k);
}

// block (256 threads) reductions
__device__ __forceinline__ float bredmax(float v, float* sh) {
    int t = threadIdx.x;
    sh[t] = v; __syncthreads();
    for (int s = 128; s > 0; s >>= 1) {
        if (t < s) sh[t] = fmaxf(sh[t], sh[t + s]);
        __syncthreads();
    }
    float r = sh[0]; __syncthreads();
    return r;
}
__device__ __forceinline__ float bredsum(float v, float* sh) {
    int t = threadIdx.x;
    sh[t] = v; __syncthreads();
    for (int s = 128; s > 0; s >>= 1) {
        if (t < s) sh[t] = sh[t] + sh[t + s];
        __syncthreads();
    }
    float r = sh[0]; __syncthreads();
    return r;
}

// ---------------- CSR build ----------------
__global__ void k_zero_deg() {
    int i = blockIdx.x * 256 + threadIdx.x;
    if (i < NN) g_deg[i] = 0;
}
__global__ void k_hist(const int* __restrict__ ei) {
    int e = blockIdx.x * 256 + threadIdx.x;
    if (e < EE) atomicAdd(&g_deg[ei[EE + e]], 1);
}
__global__ void k_scan1() {
    __shared__ int sh[1024];
    int b = blockIdx.x, t = threadIdx.x;
    int i = b * 1024 + t;
    int v = g_deg[i];
    sh[t] = v; __syncthreads();
    for (int s = 1; s < 1024; s <<= 1) {
        int a = (t >= s) ? sh[t - s] : 0;
        __syncthreads();
        sh[t] += a;
        __syncthreads();
    }
    g_off[i] = sh[t] - v;   // exclusive (local)
    if (t == 1023) g_part[b] = sh[t];
}
__global__ void k_scan2() {
    if (threadIdx.x == 0) {
        int acc = 0;
        for (int i = 0; i < 64; i++) { int v = g_part[i]; g_partoff[i] = acc; acc += v; }
    }
}
__global__ void k_scan3() {
    int i = blockIdx.x * 1024 + threadIdx.x;
    int v = g_off[i] + g_partoff[blockIdx.x];
    g_off[i] = v;
    g_pos[i] = v;
    if (i == 0) g_off[NN] = EE;
}
__global__ void k_scatter(const int* __restrict__ ei) {
    int e = blockIdx.x * 256 + threadIdx.x;
    if (e < EE) {
        int s = ei[e], d = ei[EE + e];
        int p = atomicAdd(&g_pos[d], 1);
        g_csr[p] = s;
    }
}

// ---------------- conv0: max aggregation (warp per node) ----------------
__global__ void k_agg(const float* __restrict__ x) {
    int w = blockIdx.x * 8 + (threadIdx.x >> 5);
    int l = threadIdx.x & 31;
    int beg = g_off[w], end = g_off[w + 1];
    float m0 = -INFINITY, m1 = -INFINITY;
    for (int e = beg; e < end; e++) {
        int s = g_csr[e];
        m0 = fmaxf(m0, x[s * FEAT + l]);
        m1 = fmaxf(m1, x[s * FEAT + 32 + l]);
    }
    if (beg == end) { m0 = 0.f; m1 = 0.f; }
    g_agg[w * FEAT + l] = m0;
    g_agg[w * FEAT + 32 + l] = m1;
}

// ---------------- conv0 GEMM: h = lrelu([agg|x] @ [Wrel|Wroot]^T + b0) ----------------
__global__ void __launch_bounds__(256) k_conv0(const float* __restrict__ x,
                                               const float* __restrict__ Wrel,
                                               const float* __restrict__ Wroot,
                                               const float* __restrict__ b0) {
    __shared__ float inT[32][76];
    __shared__ float Ws[32][132];
    int tid = threadIdx.x;
    int tx = tid & 15, ty = tid >> 4;
    int rbase = blockIdx.x * 64;
    float acc[4][8];
#pragma unroll
    for (int j = 0; j < 4; j++)
#pragma unroll
        for (int c = 0; c < 8; c++) acc[j][c] = 0.f;

    for (int k0 = 0; k0 < 128; k0 += 32) {
        for (int idx = tid; idx < 32 * 64; idx += 256) {
            int r = idx >> 5, kk = idx & 31;
            int kg = k0 + kk;
            float v = (kg < 64) ? g_agg[(rbase + r) * FEAT + kg]
                                : x[(rbase + r) * FEAT + (kg - 64)];
            inT[kk][r] = v;
        }
        for (int idx = tid; idx < 32 * 128; idx += 256) {
            int o = idx >> 5, kk = idx & 31;
            int kg = k0 + kk;
            float v = (kg < 64) ? Wrel[o * 64 + kg] : Wroot[o * 64 + (kg - 64)];
            Ws[kk][o] = v;
        }
        __syncthreads();
#pragma unroll
        for (int kk = 0; kk < 32; kk++) {
            float av[4], wv[8];
#pragma unroll
            for (int j = 0; j < 4; j++) av[j] = inT[kk][tx * 4 + j];
#pragma unroll
            for (int c = 0; c < 8; c++) wv[c] = Ws[kk][ty * 8 + c];
#pragma unroll
            for (int j = 0; j < 4; j++)
#pragma unroll
                for (int c = 0; c < 8; c++) acc[j][c] += av[j] * wv[c];
        }
        __syncthreads();
    }
#pragma unroll
    for (int j = 0; j < 4; j++) {
        int row = rbase + tx * 4 + j;
#pragma unroll
        for (int c = 0; c < 8; c++) {
            int col = ty * 8 + c;
            g_cur[(size_t)row * EMB + col] = lrelu(acc[j][c] + b0[col]);
        }
    }
}

// ---------------- batchnorm over g_cur (dense) ----------------
__global__ void k_bnpart() {
    int f = threadIdx.x;          // 128
    int b = blockIdx.x;           // 128 blocks x 512 rows
    float s = 0.f, ss = 0.f;
    int r0 = b * 512;
    for (int r = r0; r < r0 + 512; r++) {
        float v = g_cur[(size_t)r * EMB + f];
        s += v; ss += v * v;
    }
    g_p1[b * 128 + f] = s;
    g_p2[b * 128 + f] = ss;
}
__global__ void k_bnfin() {
    int f = threadIdx.x;
    float s = 0.f, ss = 0.f;
    for (int b = 0; b < 128; b++) { s += g_p1[b * 128 + f]; ss += g_p2[b * 128 + f]; }
    float mu = s / (float)NN;
    float var = ss / (float)NN - mu * mu;
    g_mu[f] = mu;
    g_rinv[f] = rsqrtf(var + 1e-5f);
}
__global__ void k_bnapply(const float* __restrict__ gg, const float* __restrict__ bb) {
    size_t idx = (size_t)blockIdx.x * 256 + threadIdx.x;
    int f = (int)(idx & 127);
    float v = g_cur[idx];
    g_cur[idx] = gg[f] * (v - g_mu[f]) * g_rinv[f] + bb[f];
}

// ---------------- scores: 4 dots per node ----------------
__global__ void k_scores(const float* __restrict__ w4) {
    __shared__ float ws[NHD * EMB];
    for (int idx = threadIdx.x; idx < NHD * EMB; idx += 256) ws[idx] = w4[idx];
    __syncthreads();
    int lane = threadIdx.x & 31;
    int warp = blockIdx.x * 8 + (threadIdx.x >> 5);
    int nw = gridDim.x * 8;
    for (int i = warp; i < NN; i += nw) {
        float c0 = g_cur[(size_t)i * EMB + lane];
        float c1 = g_cur[(size_t)i * EMB + 32 + lane];
        float c2 = g_cur[(size_t)i * EMB + 64 + lane];
        float c3 = g_cur[(size_t)i * EMB + 96 + lane];
#pragma unroll
        for (int h = 0; h < NHD; h++) {
            float p = c0 * ws[h * EMB + lane] + c1 * ws[h * EMB + 32 + lane] +
                      c2 * ws[h * EMB + 64 + lane] + c3 * ws[h * EMB + 96 + lane];
#pragma unroll
            for (int o = 16; o; o >>= 1) p += __shfl_down_sync(0xffffffffu, p, o);
            if (lane == 0) g_scores[h * NN + i] = p;
        }
    }
}

__global__ void k_zero_stats() {
    int t = threadIdx.x;
    if (t < 128) { g_bsum[t] = 0.f; g_bsumsq[t] = 0.f; }
    if (t < NHD) g_kcnt[t] = 0;
}

// ---------------- topk pool: per-graph softmax + keep ----------------
__global__ void k_poolkeep(float minscore) {
    __shared__ float sh[256];
    int t = threadIdx.x;
    int i = blockIdx.x * GSZ + t;
#pragma unroll
    for (int h = 0; h < NHD; h++) {
        float s = g_scores[h * NN + i];
        float m = bredmax(s, sh);
        float e = expf(s - m);
        float sum = bredsum(e, sh);
        float sm = e / (sum + 1e-16f);
        float smax = 1.0f / (sum + 1e-16f);
        float thr = fminf(smax - 1e-7f, minscore);
        bool k = sm > thr;
        g_keep[h * NN + i] = k ? 1 : 0;
        g_smv[h * NN + i] = sm;
        if (k) {
            int p = atomicAdd(&g_kcnt[h], 1);
            g_klist[h * NN + p] = i;
        }
        __syncthreads();
    }
}

__global__ void k_zero_new() {
    size_t idx = (size_t)blockIdx.x * 256 + threadIdx.x;
    g_new[idx] = 0.f;
}

__global__ void k_zero_rows() {
    int h = blockIdx.y;
    int cnt = g_kcnt[h];
    for (int idx = blockIdx.x; idx < cnt; idx += gridDim.x) {
        int i = g_klist[h * NN + idx];
        g_aggkey[((size_t)h * NN + i) * EMB + threadIdx.x] = 0u;
    }
}

// ---------------- masked edge max-aggregation (very sparse) ----------------
__global__ void k_edgescan(const int* __restrict__ ei) {
    int e = blockIdx.x * 256 + threadIdx.x;
    if (e >= EE) return;
    int s = ei[e], d = ei[EE + e];
#pragma unroll
    for (int h = 0; h < NHD; h++) {
        if (g_keep[h * NN + s] && g_keep[h * NN + d]) {
            float smv = g_smv[h * NN + s];
            unsigned* base = &g_aggkey[((size_t)h * NN + d) * EMB];
            const float* xr = &g_cur[(size_t)s * EMB];
            for (int f = 0; f < EMB; f++) atomicMax(&base[f], fenc(xr[f] * smv));
        }
    }
}

// ---------------- per-head GraphConv on kept nodes ----------------
__global__ void k_headgemm(int bi, const float* __restrict__ Wrel,
                           const float* __restrict__ Wroot, const float* __restrict__ bias) {
    int h = blockIdx.y;
    int cnt = g_kcnt[h];
    __shared__ float As[EMB], xs[EMB], pr[128];
    const float* Wr = Wrel + (size_t)((bi * NHD + h) * OUTD) * EMB;
    const float* Wo = Wroot + (size_t)((bi * NHD + h) * OUTD) * EMB;
    const float* bb = bias + (bi * NHD + h) * OUTD;
    int t = threadIdx.x;
    for (int idx = blockIdx.x; idx < cnt; idx += gridDim.x) {
        int i = g_klist[h * NN + idx];
        float smi = g_smv[h * NN + i];
        unsigned key = g_aggkey[((size_t)h * NN + i) * EMB + t];
        As[t] = key ? fdec(key) : 0.f;
        xs[t] = g_cur[(size_t)i * EMB + t] * smi;
        __syncthreads();
        int c = t & 31, q = t >> 5;
        float acc = 0.f;
#pragma unroll 8
        for (int k = q * 32; k < q * 32 + 32; k++)
            acc += As[k] * Wr[c * EMB + k] + xs[k] * Wo[c * EMB + k];
        pr[t] = acc;
        __syncthreads();
        if (t < 32) {
            float o = pr[t] + pr[t + 32] + pr[t + 64] + pr[t + 96] + bb[t];
            o = lrelu(o);
            g_new[(size_t)i * EMB + h * OUTD + t] = o;
            atomicAdd(&g_bsum[h * OUTD + t], o);
            atomicAdd(&g_bsumsq[h * OUTD + t], o * o);
        }
        __syncthreads();
    }
}

__global__ void k_bfin() {
    int f = threadIdx.x;
    float mu = g_bsum[f] / (float)NN;
    float var = g_bsumsq[f] / (float)NN - mu * mu;
    g_mu[f] = mu;
    g_rinv[f] = rsqrtf(var + 1e-5f);
}

__global__ void k_update(const float* __restrict__ gg, const float* __restrict__ bb) {
    size_t idx = (size_t)blockIdx.x * 256 + threadIdx.x;
    int f = (int)(idx & 127);
    float nv = g_new[idx];
    float bn = gg[f] * (nv - g_mu[f]) * g_rinv[f] + bb[f];
    g_cur[idx] = 0.5f * (g_cur[idx] + 0.5f * bn);
}

// ---------------- classification heads (fused pool->gate->attn->MLP) ----------------
__global__ void k_cls(const float* __restrict__ gW1, const float* __restrict__ gb1,
                      const float* __restrict__ gW2, const float* __restrict__ gb2,
                      const float* __restrict__ fW1, const float* __restrict__ fb1,
                      const float* __restrict__ fW2, const float* __restrict__ fb2) {
    __shared__ float sh[256], sms[256], xsh[EMB], gates[256], pooled[EMB], part[128];
    __shared__ int list[256];
    __shared__ int cnt;
    int g = blockIdx.x, c = blockIdx.y, t = threadIdx.x;
    int i = g * GSZ + t;
    float s = g_scores[c * NN + i];
    float m = bredmax(s, sh);
    float e = expf(s - m);
    float sum = bredsum(e, sh);
    float sm = e / (sum + 1e-16f);
    sms[t] = sm;
    float smax = 1.0f / (sum + 1e-16f);
    float thr = fminf(smax - 1e-7f, 0.8f);
    bool keep = sm > thr;
    if (t == 0) cnt = 0;
    __syncthreads();
    if (keep) { int p = atomicAdd(&cnt, 1); list[p] = t; }
    __syncthreads();
    int C = cnt;

    // gates for kept nodes
    for (int idx = 0; idx < C; idx++) {
        int tt = list[idx];
        int ii = g * GSZ + tt;
        if (t < 128) xsh[t] = g_cur[(size_t)ii * EMB + t] * sms[tt];
        __syncthreads();
        if (t < 128) {
            const float* w = gW1 + ((size_t)c * EMB + t) * EMB;
            float u = gb1[c * EMB + t];
#pragma unroll 8
            for (int k = 0; k < EMB; k++) u += xsh[k] * w[k];
            u = lrelu(u);
            part[t] = u * gW2[c * EMB + t];
        }
        __syncthreads();
        if (t < 64) part[t] += part[t + 64];
        __syncthreads();
        if (t < 32) {
            float v = part[t] + part[t + 32];
#pragma unroll
            for (int o = 16; o; o >>= 1) v += __shfl_down_sync(0xffffffffu, v, o);
            if (t == 0) gates[idx] = v + gb2[c];
        }
        __syncthreads();
    }

    // attention softmax over kept gates
    float gv = (t < C) ? gates[t] : -INFINITY;
    float m2 = bredmax(gv, sh);
    float e2 = (t < C) ? expf(gv - m2) : 0.f;
    float s2 = bredsum(e2, sh);
    float a = e2 / (s2 + 1e-16f);
    __syncthreads();
    if (t < C) gates[t] = a;
    __syncthreads();

    // pooled = sum a * xp
    if (t < 128) {
        float acc = 0.f;
        for (int idx = 0; idx < C; idx++) {
            int tt = list[idx];
            acc += gates[idx] * g_cur[(size_t)(g * GSZ + tt) * EMB + t] * sms[tt];
        }
        pooled[t] = acc;
    }
    __syncthreads();

    // final MLP -> scalar
    if (t < 128) {
        const float* w = fW1 + ((size_t)c * EMB + t) * EMB;
        float u = fb1[c * EMB + t];
#pragma unroll 8
        for (int k = 0; k < EMB; k++) u += pooled[k] * w[k];
        u = lrelu(u);
        part[t] = u * fW2[c * EMB + t];
    }
    __syncthreads();
    if (t < 64) part[t] += part[t + 64];
    __syncthreads();
    if (t < 32) {
        float v = part[t] + part[t + 32];
#pragma unroll
        for (int o = 16; o; o >>= 1) v += __shfl_down_sync(0xffffffffu, v, o);
        if (t == 0) g_logits[g * NCL + c] = v + fb2[c];
    }
}

__global__ void k_logsm(float* __restrict__ out) {
    int g = threadIdx.x;  // 256
    float l[NCL];
#pragma unroll
    for (int c = 0; c < NCL; c++) l[c] = g_logits[g * NCL + c];
    float m = l[0];
#pragma unroll
    for (int c = 1; c < NCL; c++) m = fmaxf(m, l[c]);
    float s = 0.f;
#pragma unroll
    for (int c = 0; c < NCL; c++) s += expf(l[c] - m);
    float ls = logf(s);
#pragma unroll
    for (int c = 0; c < NCL; c++) out[g * NCL + c] = l[c] - m - ls;
}

// ---------------- launch ----------------
extern "C" void kernel_launch(void* const* d_in, const int* in_sizes, int n_in,
                              void* d_out, int out_size) {
    const float* x = (const float*)d_in[0];
    const int* ei = (const int*)d_in[1];
    const float* W_rel0 = (const float*)d_in[3];
    const float* W_root0 = (const float*)d_in[4];
    const float* b0 = (const float*)d_in[5];
    const float* bn0_g = (const float*)d_in[6];
    const float* bn0_b = (const float*)d_in[7];
    const float* blk_pool_w = (const float*)d_in[8];
    const float* blk_Wrel = (const float*)d_in[9];
    const float* blk_Wroot = (const float*)d_in[10];
    const float* blk_b = (const float*)d_in[11];
    const float* blk_bn_g = (const float*)d_in[12];
    const float* blk_bn_b = (const float*)d_in[13];
    const float* cls_pool_w = (const float*)d_in[14];
    const float* cls_gW1 = (const float*)d_in[15];
    const float* cls_gb1 = (const float*)d_in[16];
    const float* cls_gW2 = (const float*)d_in[17];
    const float* cls_gb2 = (const float*)d_in[18];
    const float* cls_fW1 = (const float*)d_in[19];
    const float* cls_fb1 = (const float*)d_in[20];
    const float* cls_fW2 = (const float*)d_in[21];
    const float* cls_fb2 = (const float*)d_in[22];
    float* out = (float*)d_out;

    // CSR build
    k_zero_deg<<<NN / 256, 256>>>();
    k_hist<<<EE / 256, 256>>>(ei);
    k_scan1<<<64, 1024>>>();
    k_scan2<<<1, 32>>>();
    k_scan3<<<64, 1024>>>();
    k_scatter<<<EE / 256, 256>>>(ei);

    // conv0 + bn0
    k_agg<<<NN / 8, 256>>>(x);
    k_conv0<<<NN / 64, 256>>>(x, W_rel0, W_root0, b0);
    k_bnpart<<<128, 128>>>();
    k_bnfin<<<1, 128>>>();
    k_bnapply<<<(NN * EMB) / 256, 256>>>(bn0_g, bn0_b);

    // multi-head blocks
    for (int bi = 0; bi < NBLK; bi++) {
        k_scores<<<2048, 256>>>(blk_pool_w + (size_t)bi * NHD * EMB);
        k_zero_stats<<<1, 128>>>();
        k_poolkeep<<<GB, 256>>>(0.7f);
        k_zero_new<<<(NN * EMB) / 256, 256>>>();
        k_zero_rows<<<dim3(256, NHD), 128>>>();
        k_edgescan<<<EE / 256, 256>>>(ei);
        k_headgemm<<<dim3(256, NHD), 128>>>(bi, blk_Wrel, blk_Wroot, blk_b);
        k_bfin<<<1, 128>>>();
        k_update<<<(NN * EMB) / 256, 256>>>(blk_bn_g + bi * EMB, blk_bn_b + bi * EMB);
    }

    // classification heads
    k_scores<<<2048, 256>>>(cls_pool_w);
    k_cls<<<dim3(GB, NCL), 256>>>(cls_gW1, cls_gb1, cls_gW2, cls_gb2,
                                  cls_fW1, cls_fb1, cls_fW2, cls_fb2);
    k_logsm<<<1, 256>>>(out);
}